// round 15
// baseline (speedup 1.0000x reference)
#include <cuda_runtime.h>
#include <cuda_fp16.h>

typedef unsigned int u32;

#define BB 256
#define TT 2048
#define QD 1024
#define AD 128
#define DCH 8
#define DKK 21
#define PLL 11
#define NTHR 256

__device__ __forceinline__ float warp_sum(float v) {
#pragma unroll
    for (int o = 16; o; o >>= 1) v += __shfl_xor_sync(~0u, v, o);
    return v;
}
__device__ __forceinline__ __half2 tanh2h(u32 x) {
    u32 y; asm("tanh.approx.f16x2 %0, %1;" : "=r"(y) : "r"(x));
    return *reinterpret_cast<__half2*>(&y);
}
__device__ __forceinline__ u32 pack_f16x2(float lo, float hi) {
    u32 r; asm("cvt.rn.f16x2.f32 %0, %1, %2;" : "=r"(r) : "f"(hi), "f"(lo));
    return r;
}
// D = A(16x16 row) * B(16x8 col) + C, fp16 in / fp32 acc
__device__ __forceinline__ void mma16816(
    float& c0, float& c1, float& c2, float& c3,
    u32 a0, u32 a1, u32 a2, u32 a3, u32 b0, u32 b1)
{
    asm volatile(
        "mma.sync.aligned.m16n8k16.row.col.f32.f16.f16.f32 "
        "{%0,%1,%2,%3}, {%4,%5,%6,%7}, {%8,%9}, {%0,%1,%2,%3};"
        : "+f"(c0), "+f"(c1), "+f"(c2), "+f"(c3)
        : "r"(a0), "r"(a1), "r"(a2), "r"(a3), "r"(b0), "r"(b1));
}

__global__ __launch_bounds__(NTHR, 2) void dca_mma_kernel(
    const float* __restrict__ query,     const float* __restrict__ alignment,
    const float* __restrict__ P,         const float* __restrict__ W_w,
    const float* __restrict__ W_b,       const float* __restrict__ V_w,
    const float* __restrict__ F_w,       const float* __restrict__ U_w,
    const float* __restrict__ T_w,       const float* __restrict__ T_b,
    const float* __restrict__ v_w,       float* __restrict__ out)
{
    __shared__ __align__(16) float   sal[2080];     // fp32 padded alignment
    __shared__ __align__(16) __half  salh0[2080];   // fp16 copy
    __shared__ __align__(16) __half  salh1[2080];   // fp16 copy shifted by 1
    __shared__ __align__(16) __half  Bt[AD * 32];   // M[a][k] fp16, k 21..31 = 0
    __shared__ __align__(16) float   ep[TT];        // conv+tanh dot accumulator
    __shared__ float shq[QD];
    __shared__ float shh[AD];
    __shared__ float shG[DCH * DKK];
    __shared__ float sv[AD];
    __shared__ float sTb[AD];
    __shared__ float sp[PLL];
    __shared__ float red[8];

    const int b = blockIdx.x, tid = threadIdx.x;
    const int lane = tid & 31, wrp = tid >> 5;   // 8 warps
    const int g = lane >> 2, qi = lane & 3;

    // ---- global loads + zero init ----
    for (int i = tid; i < QD; i += NTHR) shq[i] = query[b * QD + i];
    for (int i = tid; i < TT; i += NTHR) sal[10 + i] = alignment[b * TT + i];
    if (tid < 10) sal[tid] = 0.f;
    if (tid < 22) sal[2058 + tid] = 0.f;
    if (tid < PLL) sp[tid] = P[tid];
    for (int i = tid; i < TT; i += NTHR) ep[i] = 0.f;
    __syncthreads();

    // fp16 window copies (shifted pair trick for 4B-aligned LDS.32)
    for (int j = tid; j < 2080; j += NTHR) {
        salh0[j] = __float2half_rn(sal[j]);
        salh1[j] = __float2half_rn(j + 1 < 2080 ? sal[j + 1] : 0.f);
    }

    // ---- phase A1: h[a] = tanh(dot(q, W_w[a,:]) + W_b[a])  (R7-validated) ----
    {
        float4 q[8];
#pragma unroll
        for (int j = 0; j < 8; j++) q[j] = *(const float4*)&shq[4 * lane + 128 * j];
#pragma unroll 1
        for (int i = 0; i < 16; i += 2) {
            const int a0 = wrp * 16 + i, a1 = a0 + 1;
            const float4* wr0 = (const float4*)(W_w + a0 * QD);
            const float4* wr1 = (const float4*)(W_w + a1 * QD);
            float d0 = 0.f, d1 = 0.f;
#pragma unroll
            for (int j = 0; j < 8; j++) {
                const float4 w0 = wr0[lane + 32 * j];
                const float4 w1 = wr1[lane + 32 * j];
                d0 += w0.x * q[j].x + w0.y * q[j].y + w0.z * q[j].z + w0.w * q[j].w;
                d1 += w1.x * q[j].x + w1.y * q[j].y + w1.z * q[j].z + w1.w * q[j].w;
            }
            d0 = warp_sum(d0);
            d1 = warp_sum(d1);
            if (lane == 0) {
                shh[a0] = tanhf(d0 + W_b[a0]);
                shh[a1] = tanhf(d1 + W_b[a1]);
            }
        }
    }
    __syncthreads();

    // ---- phase A2: G[r] = dot(h, V_w[r,:]) ----
    for (int r = tid; r < DCH * DKK; r += NTHR) {
        const float4* vr = (const float4*)(V_w + r * AD);
        const float4* hr = (const float4*)shh;
        float acc = 0.f;
#pragma unroll
        for (int j = 0; j < AD / 4; j++) {
            const float4 vv = vr[j], hv = hr[j];
            acc += vv.x * hv.x + vv.y * hv.y + vv.z * hv.z + vv.w * hv.w;
        }
        shG[r] = acc;
    }
    __syncthreads();

    // ---- phase A3: Bt[a][k] = M[a][k] (k<21) else 0; sv; sTb ----
    for (int i = tid; i < AD * 32; i += NTHR) {
        const int a = i >> 5, k = i & 31;
        float m = 0.f;
        if (k < DKK) {
#pragma unroll
            for (int c = 0; c < DCH; c++)
                m += U_w[a * DCH + c] * F_w[c * DKK + k]
                   + T_w[a * DCH + c] * shG[c * DKK + k];
        }
        Bt[a * 32 + k] = __float2half_rn(m);
    }
    if (tid < AD) { sv[tid] = v_w[tid]; sTb[tid] = T_b[tid]; }
    __syncthreads();

    // ---- main: HMMA over 128 slabs of 16 t-rows, 2 passes of 64 cols ----
#pragma unroll 1
    for (int pass = 0; pass < 2; pass++) {
        const int cbase = pass * 64;
        u32 bf[8][4];
        float2 v2[8], tb2[8];
#pragma unroll
        for (int nt = 0; nt < 8; nt++) {
            const int acol = cbase + nt * 8 + g;       // B frag col = g
            const u32* br = (const u32*)(Bt + acol * 32);
            bf[nt][0] = br[qi];          // k = 2i, 2i+1
            bf[nt][1] = br[qi + 4];      // k = 8+2i
            bf[nt][2] = br[qi + 8];      // k = 16+2i
            bf[nt][3] = br[qi + 12];     // k = 24+2i
            const int vcol = cbase + nt * 8 + 2 * qi;  // C frag col = 2i
            v2[nt]  = *(const float2*)&sv[vcol];
            tb2[nt] = *(const float2*)&sTb[vcol];
        }
        const u32* arrU = (const u32*)((g & 1) ? salh1 : salh0);

#pragma unroll 1
        for (int s = 0; s < 16; s++) {
            const int t0 = (wrp * 16 + s) * 16;
            const int ib = (t0 + g + 2 * qi - (g & 1)) >> 1;
            const u32 A0  = arrU[ib],      A8  = arrU[ib + 4];
            const u32 A16 = arrU[ib + 8],  A24 = arrU[ib + 12];
            const u32 A32 = arrU[ib + 16];

            float eg = 0.f, eg8 = 0.f;
#pragma unroll
            for (int nt = 0; nt < 8; nt++) {
                float c0 = tb2[nt].x, c1 = tb2[nt].y;
                float c2 = tb2[nt].x, c3 = tb2[nt].y;
                mma16816(c0, c1, c2, c3, A0,  A8,  A8,  A16, bf[nt][0], bf[nt][1]);
                mma16816(c0, c1, c2, c3, A16, A24, A24, A32, bf[nt][2], bf[nt][3]);
                const float2 f01 = __half22float2(tanh2h(pack_f16x2(c0, c1)));
                const float2 f23 = __half22float2(tanh2h(pack_f16x2(c2, c3)));
                eg  += v2[nt].x * f01.x + v2[nt].y * f01.y;
                eg8 += v2[nt].x * f23.x + v2[nt].y * f23.y;
            }
            // reduce the 4 lanes (qi) sharing rows g / g+8
            eg  += __shfl_xor_sync(~0u, eg, 1);
            eg  += __shfl_xor_sync(~0u, eg, 2);
            eg8 += __shfl_xor_sync(~0u, eg8, 1);
            eg8 += __shfl_xor_sync(~0u, eg8, 2);
            if (qi == 0) {
                ep[t0 + g]     += eg;
                ep[t0 + g + 8] += eg8;
            }
        }
    }
    __syncthreads();

    // ---- prior + softmax over T ----
    const int t0 = tid * 8;
    float e[8];
#pragma unroll
    for (int i = 0; i < 8; i++) {
        const int t = t0 + i;
        float ps = 0.f;
#pragma unroll
        for (int k = 0; k < PLL; k++) ps += sp[k] * sal[t + k];
        e[i] = ep[t] + __logf(fmaxf(ps, 1e-6f));
    }

    float mx = e[0];
#pragma unroll
    for (int i = 1; i < 8; i++) mx = fmaxf(mx, e[i]);
#pragma unroll
    for (int o = 16; o; o >>= 1) mx = fmaxf(mx, __shfl_xor_sync(~0u, mx, o));
    if (lane == 0) red[wrp] = mx;
    __syncthreads();
    mx = red[0];
#pragma unroll
    for (int i = 1; i < 8; i++) mx = fmaxf(mx, red[i]);
    __syncthreads();

    float x[8], sm = 0.f;
#pragma unroll
    for (int i = 0; i < 8; i++) { x[i] = __expf(e[i] - mx); sm += x[i]; }
#pragma unroll
    for (int o = 16; o; o >>= 1) sm += __shfl_xor_sync(~0u, sm, o);
    if (lane == 0) red[wrp] = sm;
    __syncthreads();
    sm = red[0];
#pragma unroll
    for (int i = 1; i < 8; i++) sm += red[i];

    const float inv = 1.0f / sm;
    float4* o4 = (float4*)(out + b * TT + t0);
    o4[0] = make_float4(x[0] * inv, x[1] * inv, x[2] * inv, x[3] * inv);
    o4[1] = make_float4(x[4] * inv, x[5] * inv, x[6] * inv, x[7] * inv);
}

extern "C" void kernel_launch(void* const* d_in, const int* in_sizes, int n_in,
                              void* d_out, int out_size)
{
    const float* query     = (const float*)d_in[0];
    const float* alignment = (const float*)d_in[1];
    const float* P         = (const float*)d_in[2];
    const float* W_w       = (const float*)d_in[3];
    const float* W_b       = (const float*)d_in[4];
    const float* V_w       = (const float*)d_in[5];
    const float* F_w       = (const float*)d_in[6];
    const float* U_w       = (const float*)d_in[7];
    const float* T_w       = (const float*)d_in[8];
    const float* T_b       = (const float*)d_in[9];
    const float* v_w       = (const float*)d_in[10];
    float* out = (float*)d_out;

    dca_mma_kernel<<<BB, NTHR>>>(query, alignment, P, W_w, W_b, V_w,
                                 F_w, U_w, T_w, T_b, v_w, out);
}

// round 17
// speedup vs baseline: 1.6549x; 1.6549x over previous
#include <cuda_runtime.h>
#include <cuda_fp16.h>

typedef unsigned int u32;

#define BB 256
#define TT 2048
#define QD 1024
#define AD 128
#define DCH 8
#define DKK 21
#define PLL 11
#define NTHR 256
#define EPS 2056   // ep2 row stride (floats): 8 mod 32 -> conflict-free banks

__device__ __forceinline__ float warp_sum(float v) {
#pragma unroll
    for (int o = 16; o; o >>= 1) v += __shfl_xor_sync(~0u, v, o);
    return v;
}
__device__ __forceinline__ __half2 tanh2h(u32 x) {
    u32 y; asm("tanh.approx.f16x2 %0, %1;" : "=r"(y) : "r"(x));
    return *reinterpret_cast<__half2*>(&y);
}
__device__ __forceinline__ u32 pack_f16x2(float lo, float hi) {
    u32 r; asm("cvt.rn.f16x2.f32 %0, %1, %2;" : "=r"(r) : "f"(hi), "f"(lo));
    return r;
}
// D = A(16x16 row) * B(16x8 col) + C, fp16 in / fp32 acc
__device__ __forceinline__ void mma16816(
    float& c0, float& c1, float& c2, float& c3,
    u32 a0, u32 a1, u32 a2, u32 a3, u32 b0, u32 b1)
{
    asm volatile(
        "mma.sync.aligned.m16n8k16.row.col.f32.f16.f16.f32 "
        "{%0,%1,%2,%3}, {%4,%5,%6,%7}, {%8,%9}, {%0,%1,%2,%3};"
        : "+f"(c0), "+f"(c1), "+f"(c2), "+f"(c3)
        : "r"(a0), "r"(a1), "r"(a2), "r"(a3), "r"(b0), "r"(b1));
}

__global__ __launch_bounds__(NTHR, 2) void dca_mma_kernel(
    const float* __restrict__ query,     const float* __restrict__ alignment,
    const float* __restrict__ P,         const float* __restrict__ W_w,
    const float* __restrict__ W_b,       const float* __restrict__ V_w,
    const float* __restrict__ F_w,       const float* __restrict__ U_w,
    const float* __restrict__ T_w,       const float* __restrict__ T_b,
    const float* __restrict__ v_w,       float* __restrict__ out)
{
    __shared__ __align__(16) float   sal[2080];     // fp32 padded alignment
    __shared__ __align__(16) __half  salh0[2080];   // fp16 copy
    __shared__ __align__(16) __half  salh1[2080];   // fp16 copy shifted by 1
    __shared__ __align__(16) __half  Bt[AD * 32];   // M[a][k] fp16, k 21..31 = 0
    __shared__ __align__(16) float   ep2[2][EPS];   // qi-banked partial dots
    __shared__ float shq[QD];
    __shared__ float shh[AD];
    __shared__ float shG[DCH * DKK];
    __shared__ float sv[AD];
    __shared__ float sTb[AD];
    __shared__ float sp[PLL];
    __shared__ float red[8];

    const int b = blockIdx.x, tid = threadIdx.x;
    const int lane = tid & 31, wrp = tid >> 5;   // 8 warps
    const int g = lane >> 2, qi = lane & 3;

    // ---- global loads ----
    for (int i = tid; i < QD; i += NTHR) shq[i] = query[b * QD + i];
    for (int i = tid; i < TT; i += NTHR) sal[10 + i] = alignment[b * TT + i];
    if (tid < 10) sal[tid] = 0.f;
    if (tid < 22) sal[2058 + tid] = 0.f;
    if (tid < PLL) sp[tid] = P[tid];
    __syncthreads();

    // fp16 window copies (shifted pair trick for 4B-aligned LDS.32)
    for (int j = tid; j < 2080; j += NTHR) {
        salh0[j] = __float2half_rn(sal[j]);
        salh1[j] = __float2half_rn(j + 1 < 2080 ? sal[j + 1] : 0.f);
    }

    // ---- phase A1: h[a] = tanh(dot(q, W_w[a,:]) + W_b[a]) ----
    {
        float4 q[8];
#pragma unroll
        for (int j = 0; j < 8; j++) q[j] = *(const float4*)&shq[4 * lane + 128 * j];
#pragma unroll 1
        for (int i = 0; i < 16; i += 2) {
            const int a0 = wrp * 16 + i, a1 = a0 + 1;
            const float4* wr0 = (const float4*)(W_w + a0 * QD);
            const float4* wr1 = (const float4*)(W_w + a1 * QD);
            float d0 = 0.f, d1 = 0.f;
#pragma unroll
            for (int j = 0; j < 8; j++) {
                const float4 w0 = wr0[lane + 32 * j];
                const float4 w1 = wr1[lane + 32 * j];
                d0 += w0.x * q[j].x + w0.y * q[j].y + w0.z * q[j].z + w0.w * q[j].w;
                d1 += w1.x * q[j].x + w1.y * q[j].y + w1.z * q[j].z + w1.w * q[j].w;
            }
            d0 = warp_sum(d0);
            d1 = warp_sum(d1);
            if (lane == 0) {
                shh[a0] = tanhf(d0 + W_b[a0]);
                shh[a1] = tanhf(d1 + W_b[a1]);
            }
        }
    }
    __syncthreads();

    // ---- phase A2: G[r] = dot(h, V_w[r,:]) ----
    for (int r = tid; r < DCH * DKK; r += NTHR) {
        const float4* vr = (const float4*)(V_w + r * AD);
        const float4* hr = (const float4*)shh;
        float acc = 0.f;
#pragma unroll
        for (int j = 0; j < AD / 4; j++) {
            const float4 vv = vr[j], hv = hr[j];
            acc += vv.x * hv.x + vv.y * hv.y + vv.z * hv.z + vv.w * hv.w;
        }
        shG[r] = acc;
    }
    __syncthreads();

    // ---- phase A3: Bt[a][k] = M[a][k] (k<21) else 0; sv; sTb ----
    for (int i = tid; i < AD * 32; i += NTHR) {
        const int a = i >> 5, k = i & 31;
        float m = 0.f;
        if (k < DKK) {
#pragma unroll
            for (int c = 0; c < DCH; c++)
                m += U_w[a * DCH + c] * F_w[c * DKK + k]
                   + T_w[a * DCH + c] * shG[c * DKK + k];
        }
        Bt[a * 32 + k] = __float2half_rn(m);
    }
    if (tid < AD) { sv[tid] = v_w[tid]; sTb[tid] = T_b[tid]; }
    __syncthreads();

    // ---- main: HMMA over 128 slabs of 16 t-rows, 2 passes of 64 cols ----
#pragma unroll 1
    for (int pass = 0; pass < 2; pass++) {
        const int cbase = pass * 64;
        u32 bf[8][4];
        float2 v2[8], tb2[8];
#pragma unroll
        for (int nt = 0; nt < 8; nt++) {
            const int acol = cbase + nt * 8 + g;       // B frag col = g
            const u32* br = (const u32*)(Bt + acol * 32);
            bf[nt][0] = br[qi];          // k = 2i, 2i+1
            bf[nt][1] = br[qi + 4];      // k = 8+2i
            bf[nt][2] = br[qi + 8];      // k = 16+2i
            bf[nt][3] = br[qi + 12];     // k = 24+2i
            const int vcol = cbase + nt * 8 + 2 * qi;  // C frag col = 2i
            v2[nt]  = *(const float2*)&sv[vcol];
            tb2[nt] = *(const float2*)&sTb[vcol];
        }
        const u32* arrU = (const u32*)((g & 1) ? salh1 : salh0);
        const int ib0 = (wrp * 256 + g + 2 * qi - (g & 1)) >> 1;

        // software pipeline: A fragments for s=0
        u32 A0  = arrU[ib0],      A8  = arrU[ib0 + 4];
        u32 A16 = arrU[ib0 + 8],  A24 = arrU[ib0 + 12];
        u32 A32 = arrU[ib0 + 16];

#pragma unroll 1
        for (int s = 0; s < 16; s++) {
            // prefetch s+1 fragments (hide LDS latency under HMMA+epilogue)
            u32 N0 = 0, N8 = 0, N16 = 0, N24 = 0, N32 = 0;
            if (s + 1 < 16) {
                const int ibn = ib0 + (s + 1) * 8;
                N0  = arrU[ibn];      N8  = arrU[ibn + 4];
                N16 = arrU[ibn + 8];  N24 = arrU[ibn + 12];
                N32 = arrU[ibn + 16];
            }

            float eg = 0.f, eg8 = 0.f;
#pragma unroll
            for (int nt = 0; nt < 8; nt++) {
                float c0 = tb2[nt].x, c1 = tb2[nt].y;
                float c2 = tb2[nt].x, c3 = tb2[nt].y;
                mma16816(c0, c1, c2, c3, A0,  A8,  A8,  A16, bf[nt][0], bf[nt][1]);
                mma16816(c0, c1, c2, c3, A16, A24, A24, A32, bf[nt][2], bf[nt][3]);
                const float2 f01 = __half22float2(tanh2h(pack_f16x2(c0, c1)));
                const float2 f23 = __half22float2(tanh2h(pack_f16x2(c2, c3)));
                eg  += v2[nt].x * f01.x + v2[nt].y * f01.y;
                eg8 += v2[nt].x * f23.x + v2[nt].y * f23.y;
            }
            // single shfl step: sum qi pairs; bank index qi>>1 keeps the rest
            eg  += __shfl_xor_sync(~0u, eg, 1);
            eg8 += __shfl_xor_sync(~0u, eg8, 1);
            const int t0 = (wrp * 16 + s) * 16;
            if (!(qi & 1)) {
                const int bk = qi >> 1;
                if (pass == 0) {
                    ep2[bk][t0 + g]     = eg;
                    ep2[bk][t0 + g + 8] = eg8;
                } else {
                    ep2[bk][t0 + g]     += eg;
                    ep2[bk][t0 + g + 8] += eg8;
                }
            }
            A0 = N0; A8 = N8; A16 = N16; A24 = N24; A32 = N32;
        }
        __syncthreads();
    }

    // ---- prior + bank-fold + softmax over T ----
    const int t0 = tid * 8;
    float e[8];
#pragma unroll
    for (int i = 0; i < 8; i++) {
        const int t = t0 + i;
        float ps = 0.f;
#pragma unroll
        for (int k = 0; k < PLL; k++) ps += sp[k] * sal[t + k];
        e[i] = ep2[0][t] + ep2[1][t] + __logf(fmaxf(ps, 1e-6f));
    }

    float mx = e[0];
#pragma unroll
    for (int i = 1; i < 8; i++) mx = fmaxf(mx, e[i]);
#pragma unroll
    for (int o = 16; o; o >>= 1) mx = fmaxf(mx, __shfl_xor_sync(~0u, mx, o));
    if (lane == 0) red[wrp] = mx;
    __syncthreads();
    mx = red[0];
#pragma unroll
    for (int i = 1; i < 8; i++) mx = fmaxf(mx, red[i]);
    __syncthreads();

    float x[8], sm = 0.f;
#pragma unroll
    for (int i = 0; i < 8; i++) { x[i] = __expf(e[i] - mx); sm += x[i]; }
#pragma unroll
    for (int o = 16; o; o >>= 1) sm += __shfl_xor_sync(~0u, sm, o);
    if (lane == 0) red[wrp] = sm;
    __syncthreads();
    sm = red[0];
#pragma unroll
    for (int i = 1; i < 8; i++) sm += red[i];

    const float inv = 1.0f / sm;
    float4* o4 = (float4*)(out + b * TT + t0);
    o4[0] = make_float4(x[0] * inv, x[1] * inv, x[2] * inv, x[3] * inv);
    o4[1] = make_float4(x[4] * inv, x[5] * inv, x[6] * inv, x[7] * inv);
}

extern "C" void kernel_launch(void* const* d_in, const int* in_sizes, int n_in,
                              void* d_out, int out_size)
{
    const float* query     = (const float*)d_in[0];
    const float* alignment = (const float*)d_in[1];
    const float* P         = (const float*)d_in[2];
    const float* W_w       = (const float*)d_in[3];
    const float* W_b       = (const float*)d_in[4];
    const float* V_w       = (const float*)d_in[5];
    const float* F_w       = (const float*)d_in[6];
    const float* U_w       = (const float*)d_in[7];
    const float* T_w       = (const float*)d_in[8];
    const float* T_b       = (const float*)d_in[9];
    const float* v_w       = (const float*)d_in[10];
    float* out = (float*)d_out;

    dca_mma_kernel<<<BB, NTHR>>>(query, alignment, P, W_w, W_b, V_w,
                                 F_w, U_w, T_w, T_b, v_w, out);
}